// round 15
// baseline (speedup 1.0000x reference)
#include <cuda_runtime.h>
#include <cuda_bf16.h>
#include <math.h>
#include <cstdint>

// Problem constants
#define NN   1024
#define DD   128
#define DIN  137
#define NL   3
#define ACR  4
#define MPOW 12     // powers c^1..c^12 (gelu poly degree 12 in z)

// gelu(x) = z*(C) + sum_t ECtS * z^(2t+2),  z = x/sqrt(2) (pre-scaled a,c)
#define EC0S  7.9788456080e-1f
#define EC1S -2.6596152027e-1f
#define EC2S  7.9788456080e-2f
#define EC3S -1.8997270260e-2f
#define EC4S  3.6939104237e-3f
#define EC5S -6.0446590722e-4f
#define CSQ2  7.0710678119e-1f

// ---------------- scratch (device globals; no allocation allowed) -----------
__device__ float g_h  [NN * DD];
__device__ float g_a  [NN * DD];    // pre-scaled by 1/sqrt(2)
__device__ float g_cb [NN * DD];    // (c + bm) pre-scaled by 1/sqrt(2)
__device__ float g_agg[NN * DD];
__device__ __nv_bfloat16 g_adjb[NN * NN];            // adj in bf16 (once)
__device__ float g_S0 [NN];                          // adj row sums (once)
__device__ __nv_bfloat16 g_pow[(size_t)MPOW * DD * NN];  // [m][d][j]
__device__ float g_S  [(size_t)MPOW * NN * DD];      // [m][i][d]

__device__ __forceinline__ float gelu_exact(float x) {
    return 0.5f * x * (1.0f + erff(x * 0.70710678118654752f));
}

// ============ kernel P: adj -> bf16 + row sums (once per launch) ============
__global__ void k_prep(const float* __restrict__ adj) {
    int i = blockIdx.x, tid = threadIdx.x;
    float s = 0.0f;
    for (int j = tid; j < NN; j += 256) {
        float v = adj[(size_t)i * NN + j];
        g_adjb[(size_t)i * NN + j] = __float2bfloat16(v);
        s += v;
    }
    #pragma unroll
    for (int o = 16; o > 0; o >>= 1) s += __shfl_xor_sync(0xffffffffu, s, o);
    __shared__ float r[8];
    if ((tid & 31) == 0) r[tid >> 5] = s;
    __syncthreads();
    if (tid == 0) {
        float t = 0.0f;
        #pragma unroll
        for (int k = 0; k < 8; ++k) t += r[k];
        g_S0[i] = t;
    }
}

// ============ kernel A: proj + a/c of layer 0 (fused, k-split) ==============
__global__ void k_proj_ac(const float* __restrict__ nf,
                          const float* __restrict__ Wp,
                          const float* __restrict__ bp,
                          const float* __restrict__ Wm,
                          const float* __restrict__ bm) {
    int i0 = blockIdx.x * ACR;
    int d  = threadIdx.x;
    int ty = threadIdx.y;
    int tid = ty * DD + d;

    __shared__ float sh[ACR][DIN + 3];
    __shared__ float hn[ACR][DD];
    __shared__ float red[ACR][ACR][DD];

    for (int e = tid; e < ACR * DIN; e += ACR * DD) {
        int r = e / DIN, c = e % DIN;
        sh[r][c] = nf[(i0 + r) * DIN + c];
    }
    __syncthreads();
    {
        int k0 = (ty * DIN) / ACR, k1 = ((ty + 1) * DIN) / ACR;
        float acc[ACR] = {0.f, 0.f, 0.f, 0.f};
        for (int k = k0; k < k1; ++k) {
            float w = Wp[k * DD + d];
            #pragma unroll
            for (int r = 0; r < ACR; ++r) acc[r] = fmaf(sh[r][k], w, acc[r]);
        }
        #pragma unroll
        for (int r = 0; r < ACR; ++r) red[ty][r][d] = acc[r];
    }
    __syncthreads();
    {
        float h = bp[d] + red[0][ty][d] + red[1][ty][d] + red[2][ty][d] + red[3][ty][d];
        g_h[(i0 + ty) * DD + d] = h;
        hn[ty][d] = h;
    }
    __syncthreads();
    const float* WA = Wm;
    const float* WC = Wm + DD * DD;
    float aa[ACR] = {0.f, 0.f, 0.f, 0.f};
    float cc[ACR] = {0.f, 0.f, 0.f, 0.f};
    int k0 = ty * 32;
    #pragma unroll 8
    for (int kk = 0; kk < 32; ++kk) {
        int k = k0 + kk;
        float wa = WA[k * DD + d];
        float wc = WC[k * DD + d];
        #pragma unroll
        for (int r = 0; r < ACR; ++r) {
            float hv = hn[r][k];
            aa[r] = fmaf(hv, wa, aa[r]);
            cc[r] = fmaf(hv, wc, cc[r]);
        }
    }
    #pragma unroll
    for (int r = 0; r < ACR; ++r) red[ty][r][d] = aa[r];
    __syncthreads();
    g_a[(i0 + ty) * DD + d] =
        (red[0][ty][d] + red[1][ty][d] + red[2][ty][d] + red[3][ty][d]) * CSQ2;
    __syncthreads();
    #pragma unroll
    for (int r = 0; r < ACR; ++r) red[ty][r][d] = cc[r];
    __syncthreads();
    g_cb[(i0 + ty) * DD + d] =
        (red[0][ty][d] + red[1][ty][d] + red[2][ty][d] + red[3][ty][d] + bm[d]) * CSQ2;
}

// ============ kernel W: powers of c, transposed to [m][d][j] bf16 ===========
__global__ void k_pow() {
    __shared__ float sm[32][33];
    int j0 = blockIdx.x * 32, d0 = blockIdx.y * 32;
    int tx = threadIdx.x, ty = threadIdx.y;
    sm[ty][tx] = g_cb[(j0 + ty) * DD + d0 + tx];
    __syncthreads();
    float v = sm[tx][ty];      // = cv[j0+tx][d0+ty]
    float p = v;
    #pragma unroll
    for (int m = 0; m < MPOW; ++m) {
        g_pow[((size_t)m * DD + d0 + ty) * NN + j0 + tx] = __float2bfloat16(p);
        p *= v;
    }
}

// ============ kernel G: S[m][i][d] = adj @ c^m via mma.sync bf16 ============
// smem-tiled + register-prefetch pipeline. Block 256 thr (8 warps:
// 2 row-groups x 4 col-groups), tile 32 x 128, K chunks of 64.
// grid (32 i-tiles, MPOW) = 384 CTAs.
#define SAS 72   // smem row stride in bf16 (64 data + 8 pad -> conflict-free)
__global__ __launch_bounds__(256) void k_gemm() {
    int i0 = blockIdx.x * 32;
    int mi = blockIdx.y;               // power index 0..11 (c^(mi+1))
    int tid = threadIdx.x;
    int lane = tid & 31;
    int wid = tid >> 5;
    int wr = wid & 1;                  // 0..1 row group (16 rows)
    int wc = wid >> 1;                 // 0..3 col group (32 cols)
    int lr = lane >> 2;                // 0..7
    int lc = lane & 3;                 // 0..3

    __shared__ __nv_bfloat16 sA[32 * SAS];
    __shared__ __nv_bfloat16 sB[128 * SAS];

    const __nv_bfloat16* A = g_adjb;                        // [i][j]
    const __nv_bfloat16* B = g_pow + (size_t)mi * DD * NN;  // [d][j]

    float acc[4][4];
    #pragma unroll
    for (int nt = 0; nt < 4; ++nt) {
        acc[nt][0] = 0.f; acc[nt][1] = 0.f; acc[nt][2] = 0.f; acc[nt][3] = 0.f;
    }

    int arow = wr * 16 + lr;
    // staging indices (per thread): sA 1 uint4, sB 4 uint4
    int ar = tid >> 3, aq = tid & 7;               // sA: row 0..31, q 0..7
    const uint4* gAp = (const uint4*)&A[(size_t)(i0 + ar) * NN + aq * 8];
    uint4* sAp = (uint4*)&sA[ar * SAS + aq * 8];

    uint4 ra, rb[4];
    // prologue: load chunk 0
    ra = gAp[0];
    #pragma unroll
    for (int u = 0; u < 4; ++u) {
        int e = tid + 256 * u;
        int r = e >> 3, q = e & 7;
        rb[u] = *(const uint4*)&B[(size_t)r * NN + q * 8];
    }

    for (int ch = 0; ch < 16; ++ch) {
        // store staged regs -> smem
        *sAp = ra;
        #pragma unroll
        for (int u = 0; u < 4; ++u) {
            int e = tid + 256 * u;
            int r = e >> 3, q = e & 7;
            *(uint4*)&sB[r * SAS + q * 8] = rb[u];
        }
        __syncthreads();

        // prefetch next chunk into regs (LDGs drain during mma below)
        if (ch < 15) {
            int k0n = (ch + 1) * 64;
            ra = gAp[k0n / 8];
            #pragma unroll
            for (int u = 0; u < 4; ++u) {
                int e = tid + 256 * u;
                int r = e >> 3, q = e & 7;
                rb[u] = *(const uint4*)&B[(size_t)r * NN + k0n + q * 8];
            }
        }

        #pragma unroll
        for (int ks = 0; ks < 4; ++ks) {
            int kb = ks * 16;
            uint32_t a0 = *(const uint32_t*)&sA[arow * SAS + kb + lc * 2];
            uint32_t a1 = *(const uint32_t*)&sA[(arow + 8) * SAS + kb + lc * 2];
            uint32_t a2 = *(const uint32_t*)&sA[arow * SAS + kb + 8 + lc * 2];
            uint32_t a3 = *(const uint32_t*)&sA[(arow + 8) * SAS + kb + 8 + lc * 2];
            #pragma unroll
            for (int nt = 0; nt < 4; ++nt) {
                int brow = wc * 32 + nt * 8 + lr;
                uint32_t b0 = *(const uint32_t*)&sB[brow * SAS + kb + lc * 2];
                uint32_t b1 = *(const uint32_t*)&sB[brow * SAS + kb + 8 + lc * 2];
                asm volatile(
                    "mma.sync.aligned.m16n8k16.row.col.f32.bf16.bf16.f32 "
                    "{%0,%1,%2,%3}, {%4,%5,%6,%7}, {%8,%9}, {%0,%1,%2,%3};"
                    : "+f"(acc[nt][0]), "+f"(acc[nt][1]),
                      "+f"(acc[nt][2]), "+f"(acc[nt][3])
                    : "r"(a0), "r"(a1), "r"(a2), "r"(a3), "r"(b0), "r"(b1));
            }
        }
        __syncthreads();   // all reads done before next store overwrites
    }

    float* S = g_S + (size_t)mi * NN * DD;
    int row = i0 + wr * 16 + lr;
    #pragma unroll
    for (int nt = 0; nt < 4; ++nt) {
        int c0 = wc * 32 + nt * 8 + lc * 2;
        *(float2*)&S[(size_t)row * DD + c0] =
            make_float2(acc[nt][0], acc[nt][1]);
        *(float2*)&S[(size_t)(row + 8) * DD + c0] =
            make_float2(acc[nt][2], acc[nt][3]);
    }
}

// ============ kernel Cb: combine S_m into agg ================================
__device__ const float QC[13][6] = {
    {EC0S,        EC1S,        EC2S,        EC3S,         EC4S,         EC5S},
    {2*EC0S,      4*EC1S,      6*EC2S,      8*EC3S,       10*EC4S,      12*EC5S},
    {EC0S,        6*EC1S,      15*EC2S,     28*EC3S,      45*EC4S,      66*EC5S},
    {0.f,         4*EC1S,      20*EC2S,     56*EC3S,      120*EC4S,     220*EC5S},
    {0.f,         EC1S,        15*EC2S,     70*EC3S,      210*EC4S,     495*EC5S},
    {0.f,         0.f,         6*EC2S,      56*EC3S,      252*EC4S,     792*EC5S},
    {0.f,         0.f,         EC2S,        28*EC3S,      210*EC4S,     924*EC5S},
    {0.f,         0.f,         0.f,         8*EC3S,       120*EC4S,     792*EC5S},
    {0.f,         0.f,         0.f,         EC3S,         45*EC4S,      495*EC5S},
    {0.f,         0.f,         0.f,         0.f,          10*EC4S,      220*EC5S},
    {0.f,         0.f,         0.f,         0.f,          EC4S,         66*EC5S},
    {0.f,         0.f,         0.f,         0.f,          0.f,          12*EC5S},
    {0.f,         0.f,         0.f,         0.f,          0.f,          EC5S}
};

__global__ void k_comb() {
    int i = blockIdx.x, d = threadIdx.x;
    float av = g_a[i * DD + d];
    float s0 = g_S0[i];
    float avp[13];
    avp[0] = 1.0f;
    #pragma unroll
    for (int k = 1; k <= 12; ++k) avp[k] = avp[k - 1] * av;

    float acc = 0.0f;
    #pragma unroll
    for (int m = 0; m <= 12; ++m) {
        float w = 0.0f;
        #pragma unroll
        for (int t = 0; t < 6; ++t) {
            if (2 * t + 2 >= m) w = fmaf(QC[m][t], avp[2 * t + 2 - m], w);
        }
        if (m == 0) w = fmaf(CSQ2, av, w);       // C*z term, a-part
        if (m == 1) w += CSQ2;                   // C*z term, c-part
        float Sm = (m == 0) ? s0 : g_S[((size_t)(m - 1) * NN + i) * DD + d];
        acc = fmaf(w, Sm, acc);
    }
    g_agg[i * DD + d] = acc;
}

// ====== kernel C: update+LN (+ a/c of next layer) fused, k-split ============
__global__ void k_upac(const float* __restrict__ Wu,
                       const float* __restrict__ bu,
                       const float* __restrict__ gamma,
                       const float* __restrict__ beta,
                       const float* __restrict__ Wm,
                       const float* __restrict__ bm,
                       int l, int do_next) {
    int i0 = blockIdx.x * ACR;
    int d  = threadIdx.x;
    int ty = threadIdx.y;
    int tid = ty * DD + d;

    __shared__ float hsh[ACR][DD], ash[ACR][DD], newh[ACR][DD];
    __shared__ float red[ACR][ACR][DD];
    __shared__ float rs_m[ACR][4], rs_v[ACR][4];

    {
        int r = tid >> 7, c = tid & 127;
        hsh[r][c] = g_h  [(i0 + r) * DD + c];
        ash[r][c] = g_agg[(i0 + r) * DD + c];
    }
    __syncthreads();

    const float* W1 = Wu + (size_t)l * 2 * DD * DD;
    const float* W2 = W1 + DD * DD;
    {
        float acc[ACR] = {0.f, 0.f, 0.f, 0.f};
        int k0 = ty * 32;
        #pragma unroll 8
        for (int kk = 0; kk < 32; ++kk) {
            int k = k0 + kk;
            float w1 = W1[k * DD + d];
            float w2 = W2[k * DD + d];
            #pragma unroll
            for (int r = 0; r < ACR; ++r) {
                acc[r] = fmaf(hsh[r][k], w1, acc[r]);
                acc[r] = fmaf(ash[r][k], w2, acc[r]);
            }
        }
        #pragma unroll
        for (int r = 0; r < ACR; ++r) red[ty][r][d] = acc[r];
    }
    __syncthreads();

    int r = ty;
    float x = bu[l * DD + d]
            + red[0][r][d] + red[1][r][d] + red[2][r][d] + red[3][r][d];
    x = gelu_exact(x) + hsh[r][d];

    float v = x;
    #pragma unroll
    for (int o = 16; o > 0; o >>= 1) v += __shfl_xor_sync(0xffffffffu, v, o);
    if ((d & 31) == 0) rs_m[r][d >> 5] = v;
    __syncthreads();
    float mean = (rs_m[r][0] + rs_m[r][1] + rs_m[r][2] + rs_m[r][3]) * (1.0f / DD);
    float xm = x - mean;
    float v2 = xm * xm;
    #pragma unroll
    for (int o = 16; o > 0; o >>= 1) v2 += __shfl_xor_sync(0xffffffffu, v2, o);
    if ((d & 31) == 0) rs_v[r][d >> 5] = v2;
    __syncthreads();
    float var = (rs_v[r][0] + rs_v[r][1] + rs_v[r][2] + rs_v[r][3]) * (1.0f / DD);
    float y = xm * rsqrtf(var + 1e-5f) * gamma[l * DD + d] + beta[l * DD + d];
    g_h[(i0 + r) * DD + d] = y;
    newh[r][d] = y;
    __syncthreads();

    if (do_next) {
        const float* WA = Wm + (size_t)(l + 1) * 2 * DD * DD;
        const float* WC = WA + DD * DD;
        float aa[ACR] = {0.f, 0.f, 0.f, 0.f};
        float cc[ACR] = {0.f, 0.f, 0.f, 0.f};
        int k0 = ty * 32;
        #pragma unroll 8
        for (int kk = 0; kk < 32; ++kk) {
            int k = k0 + kk;
            float wa = WA[k * DD + d];
            float wc = WC[k * DD + d];
            #pragma unroll
            for (int rr = 0; rr < ACR; ++rr) {
                float hv = newh[rr][k];
                aa[rr] = fmaf(hv, wa, aa[rr]);
                cc[rr] = fmaf(hv, wc, cc[rr]);
            }
        }
        #pragma unroll
        for (int rr = 0; rr < ACR; ++rr) red[ty][rr][d] = aa[rr];
        __syncthreads();
        g_a[(i0 + ty) * DD + d] =
            (red[0][ty][d] + red[1][ty][d] + red[2][ty][d] + red[3][ty][d]) * CSQ2;
        __syncthreads();
        #pragma unroll
        for (int rr = 0; rr < ACR; ++rr) red[ty][rr][d] = cc[rr];
        __syncthreads();
        g_cb[(i0 + ty) * DD + d] =
            (red[0][ty][d] + red[1][ty][d] + red[2][ty][d] + red[3][ty][d]
             + bm[(l + 1) * DD + d]) * CSQ2;
    }
}

// ---------------- kernel D: output heads ------------------------------------
__global__ void k_heads(const float* __restrict__ Wt,
                        const float* __restrict__ bt,
                        const float* __restrict__ Wi,
                        const float* __restrict__ bi,
                        const float* __restrict__ Wa,
                        const float* __restrict__ ba,
                        float* __restrict__ out) {
    int i = blockIdx.x;
    int d = threadIdx.x;
    __shared__ float hsh[DD];
    float hv = g_h[i * DD + d];
    hsh[d] = hv;
    __syncthreads();

    out[NN + NN * 5 + NN * 5 + i * DD + d] = hv;

    if (d < 5) {
        float s = bi[d];
        #pragma unroll 8
        for (int k = 0; k < DD; ++k) s = fmaf(hsh[k], Wi[k * 5 + d], s);
        out[NN + i * 5 + d] = s;
        float s2 = ba[d];
        #pragma unroll 8
        for (int k = 0; k < DD; ++k) s2 = fmaf(hsh[k], Wa[k * 5 + d], s2);
        out[NN + NN * 5 + i * 5 + d] = s2;
    }
    if (d == 5) {
        float s = bt[0];
        #pragma unroll 8
        for (int k = 0; k < DD; ++k) s = fmaf(hsh[k], Wt[k], s);
        out[i] = 5.0f / (1.0f + expf(-s));
    }
}

// ---------------- launcher ---------------------------------------------------
extern "C" void kernel_launch(void* const* d_in, const int* in_sizes, int n_in,
                              void* d_out, int out_size) {
    const float* nf    = (const float*)d_in[0];
    const float* adj   = (const float*)d_in[1];
    const float* Wp    = (const float*)d_in[2];
    const float* bp    = (const float*)d_in[3];
    const float* Wm    = (const float*)d_in[4];
    const float* bm    = (const float*)d_in[5];
    const float* Wu    = (const float*)d_in[6];
    const float* bu    = (const float*)d_in[7];
    const float* gamma = (const float*)d_in[8];
    const float* beta  = (const float*)d_in[9];
    const float* Wt    = (const float*)d_in[10];
    const float* bt    = (const float*)d_in[11];
    const float* Wi    = (const float*)d_in[12];
    const float* bi    = (const float*)d_in[13];
    const float* Wa    = (const float*)d_in[14];
    const float* ba    = (const float*)d_in[15];
    float* out = (float*)d_out;

    k_prep<<<NN, 256>>>(adj);
    dim3 gblk(DD, ACR);
    k_proj_ac<<<NN / ACR, gblk>>>(nf, Wp, bp, Wm, bm);
    for (int l = 0; l < NL; ++l) {
        k_pow<<<dim3(NN / 32, DD / 32), dim3(32, 32)>>>();
        k_gemm<<<dim3(32, MPOW), 256>>>();
        k_comb<<<NN, DD>>>();
        k_upac<<<NN / ACR, gblk>>>(Wu, bu, gamma, beta, Wm, bm, l, (l + 1 < NL) ? 1 : 0);
    }
    k_heads<<<NN, DD>>>(Wt, bt, Wi, bi, Wa, ba, out);
}

// round 16
// speedup vs baseline: 1.0123x; 1.0123x over previous
#include <cuda_runtime.h>
#include <cuda_bf16.h>
#include <math.h>
#include <cstdint>

// Problem constants
#define NN   1024
#define DD   128
#define DIN  137
#define NL   3
#define ACR  4
#define MPOW 12     // powers c^1..c^12 (gelu poly degree 12 in z)

// gelu(x) = z*(C) + sum_t ECtS * z^(2t+2),  z = x/sqrt(2) (pre-scaled a,c)
#define EC0S  7.9788456080e-1f
#define EC1S -2.6596152027e-1f
#define EC2S  7.9788456080e-2f
#define EC3S -1.8997270260e-2f
#define EC4S  3.6939104237e-3f
#define EC5S -6.0446590722e-4f
#define CSQ2  7.0710678119e-1f

// ---------------- scratch (device globals; no allocation allowed) -----------
__device__ float g_h  [NN * DD];
__device__ float g_a  [NN * DD];    // pre-scaled by 1/sqrt(2)
__device__ float g_cb [NN * DD];    // (c + bm) pre-scaled by 1/sqrt(2)
__device__ float g_agg[NN * DD];
__device__ __nv_bfloat16 g_adjb[NN * NN];            // adj in bf16 (once)
__device__ float g_S0 [NN];                          // adj row sums (once)
__device__ __nv_bfloat16 g_pow[(size_t)MPOW * DD * NN];  // [m][d][j]
__device__ float g_S  [(size_t)MPOW * NN * DD];      // [m][i][d]

__device__ __forceinline__ float gelu_exact(float x) {
    return 0.5f * x * (1.0f + erff(x * 0.70710678118654752f));
}

// ============ kernel P: adj -> bf16 + row sums (once per launch) ============
__global__ void k_prep(const float* __restrict__ adj) {
    int i = blockIdx.x, tid = threadIdx.x;
    float s = 0.0f;
    for (int j = tid; j < NN; j += 256) {
        float v = adj[(size_t)i * NN + j];
        g_adjb[(size_t)i * NN + j] = __float2bfloat16(v);
        s += v;
    }
    #pragma unroll
    for (int o = 16; o > 0; o >>= 1) s += __shfl_xor_sync(0xffffffffu, s, o);
    __shared__ float r[8];
    if ((tid & 31) == 0) r[tid >> 5] = s;
    __syncthreads();
    if (tid == 0) {
        float t = 0.0f;
        #pragma unroll
        for (int k = 0; k < 8; ++k) t += r[k];
        g_S0[i] = t;
    }
}

// ============ kernel A: proj + a/c of layer 0 (fused, k-split) ==============
__global__ void k_proj_ac(const float* __restrict__ nf,
                          const float* __restrict__ Wp,
                          const float* __restrict__ bp,
                          const float* __restrict__ Wm,
                          const float* __restrict__ bm) {
    int i0 = blockIdx.x * ACR;
    int d  = threadIdx.x;
    int ty = threadIdx.y;
    int tid = ty * DD + d;

    __shared__ float sh[ACR][DIN + 3];
    __shared__ float hn[ACR][DD];
    __shared__ float red[ACR][ACR][DD];

    for (int e = tid; e < ACR * DIN; e += ACR * DD) {
        int r = e / DIN, c = e % DIN;
        sh[r][c] = nf[(i0 + r) * DIN + c];
    }
    __syncthreads();
    {
        int k0 = (ty * DIN) / ACR, k1 = ((ty + 1) * DIN) / ACR;
        float acc[ACR] = {0.f, 0.f, 0.f, 0.f};
        for (int k = k0; k < k1; ++k) {
            float w = Wp[k * DD + d];
            #pragma unroll
            for (int r = 0; r < ACR; ++r) acc[r] = fmaf(sh[r][k], w, acc[r]);
        }
        #pragma unroll
        for (int r = 0; r < ACR; ++r) red[ty][r][d] = acc[r];
    }
    __syncthreads();
    {
        float h = bp[d] + red[0][ty][d] + red[1][ty][d] + red[2][ty][d] + red[3][ty][d];
        g_h[(i0 + ty) * DD + d] = h;
        hn[ty][d] = h;
    }
    __syncthreads();
    const float* WA = Wm;
    const float* WC = Wm + DD * DD;
    float aa[ACR] = {0.f, 0.f, 0.f, 0.f};
    float cc[ACR] = {0.f, 0.f, 0.f, 0.f};
    int k0 = ty * 32;
    #pragma unroll 8
    for (int kk = 0; kk < 32; ++kk) {
        int k = k0 + kk;
        float wa = WA[k * DD + d];
        float wc = WC[k * DD + d];
        #pragma unroll
        for (int r = 0; r < ACR; ++r) {
            float hv = hn[r][k];
            aa[r] = fmaf(hv, wa, aa[r]);
            cc[r] = fmaf(hv, wc, cc[r]);
        }
    }
    #pragma unroll
    for (int r = 0; r < ACR; ++r) red[ty][r][d] = aa[r];
    __syncthreads();
    g_a[(i0 + ty) * DD + d] =
        (red[0][ty][d] + red[1][ty][d] + red[2][ty][d] + red[3][ty][d]) * CSQ2;
    __syncthreads();
    #pragma unroll
    for (int r = 0; r < ACR; ++r) red[ty][r][d] = cc[r];
    __syncthreads();
    g_cb[(i0 + ty) * DD + d] =
        (red[0][ty][d] + red[1][ty][d] + red[2][ty][d] + red[3][ty][d] + bm[d]) * CSQ2;
}

// ============ kernel W: powers of c, transposed to [m][d][j] bf16 ===========
__global__ void k_pow() {
    __shared__ float sm[32][33];
    int j0 = blockIdx.x * 32, d0 = blockIdx.y * 32;
    int tx = threadIdx.x, ty = threadIdx.y;
    sm[ty][tx] = g_cb[(j0 + ty) * DD + d0 + tx];
    __syncthreads();
    float v = sm[tx][ty];      // = cv[j0+tx][d0+ty]
    float p = v;
    #pragma unroll
    for (int m = 0; m < MPOW; ++m) {
        g_pow[((size_t)m * DD + d0 + ty) * NN + j0 + tx] = __float2bfloat16(p);
        p *= v;
    }
}

// ============ kernel G: S[m][i][d] = adj @ c^m via mma.sync bf16 ============
// smem-tiled + register-prefetch + ldmatrix fragment loads.
// Block 256 thr (8 warps: 2 row-groups x 4 col-groups), tile 32 x 128,
// K chunks of 64. grid (32 i-tiles, MPOW) = 384 CTAs.
#define SAS 72   // smem row stride in bf16 (64 data + 8 pad -> conflict-free)
__global__ __launch_bounds__(256) void k_gemm() {
    int i0 = blockIdx.x * 32;
    int mi = blockIdx.y;               // power index 0..11 (c^(mi+1))
    int tid = threadIdx.x;
    int lane = tid & 31;
    int wid = tid >> 5;
    int wr = wid & 1;                  // 0..1 row group (16 rows)
    int wc = wid >> 1;                 // 0..3 col group (32 cols)
    int lr = lane >> 2;                // 0..7
    int lc = lane & 3;                 // 0..3

    __shared__ __nv_bfloat16 sA[32 * SAS];
    __shared__ __nv_bfloat16 sB[128 * SAS];

    const __nv_bfloat16* A = g_adjb;                        // [i][j]
    const __nv_bfloat16* B = g_pow + (size_t)mi * DD * NN;  // [d][j]

    float acc[4][4];
    #pragma unroll
    for (int nt = 0; nt < 4; ++nt) {
        acc[nt][0] = 0.f; acc[nt][1] = 0.f; acc[nt][2] = 0.f; acc[nt][3] = 0.f;
    }

    // ---- ldmatrix per-lane base addresses (shared-space u32) ----
    // A x4: groups(l>>3): 0: rows r..r+7 @k, 1: r+8.. @k, 2: r.. @k+8, 3: r+8 @k+8
    uint32_t aRow = wr * 16 + (lane & 7) + ((lane >> 3) & 1) * 8;
    uint32_t aCol = ((lane >> 4) & 1) * 8;
    uint32_t aAddr = (uint32_t)__cvta_generic_to_shared(
        &sA[aRow * SAS + aCol]);
    // B x4 for nt-pair (p, p+1): groups: 0: rows n(p) @k, 1: n(p) @k+8,
    //                                     2: n(p+1) @k, 3: n(p+1) @k+8
    uint32_t bRow = wc * 32 + ((lane >> 4) & 1) * 8 + (lane & 7);
    uint32_t bCol = ((lane >> 3) & 1) * 8;
    uint32_t bAddr0 = (uint32_t)__cvta_generic_to_shared(
        &sB[bRow * SAS + bCol]);                 // nt pair {0,1}
    uint32_t bAddr1 = bAddr0 + 16 * SAS * 2;     // nt pair {2,3}

    // staging indices (per thread): sA 1 uint4, sB 4 uint4
    int ar = tid >> 3, aq = tid & 7;               // sA: row 0..31, q 0..7
    const uint4* gAp = (const uint4*)&A[(size_t)(i0 + ar) * NN + aq * 8];
    uint4* sAp = (uint4*)&sA[ar * SAS + aq * 8];

    uint4 ra, rb[4];
    // prologue: load chunk 0
    ra = gAp[0];
    #pragma unroll
    for (int u = 0; u < 4; ++u) {
        int e = tid + 256 * u;
        int r = e >> 3, q = e & 7;
        rb[u] = *(const uint4*)&B[(size_t)r * NN + q * 8];
    }

    for (int ch = 0; ch < 16; ++ch) {
        // store staged regs -> smem
        *sAp = ra;
        #pragma unroll
        for (int u = 0; u < 4; ++u) {
            int e = tid + 256 * u;
            int r = e >> 3, q = e & 7;
            *(uint4*)&sB[r * SAS + q * 8] = rb[u];
        }
        __syncthreads();

        // prefetch next chunk into regs (LDGs drain during mma below)
        if (ch < 15) {
            int k0n = (ch + 1) * 64;
            ra = gAp[k0n / 8];
            #pragma unroll
            for (int u = 0; u < 4; ++u) {
                int e = tid + 256 * u;
                int r = e >> 3, q = e & 7;
                rb[u] = *(const uint4*)&B[(size_t)r * NN + k0n + q * 8];
            }
        }

        #pragma unroll
        for (int ks = 0; ks < 4; ++ks) {
            uint32_t kOff = ks * 16 * 2;   // bytes
            uint32_t a0, a1, a2, a3;
            asm volatile(
                "ldmatrix.sync.aligned.m8n8.x4.shared.b16 {%0,%1,%2,%3}, [%4];"
                : "=r"(a0), "=r"(a1), "=r"(a2), "=r"(a3)
                : "r"(aAddr + kOff));
            uint32_t b00, b01, b10, b11;   // {b0 nt, b1 nt, b0 nt+1, b1 nt+1}
            asm volatile(
                "ldmatrix.sync.aligned.m8n8.x4.shared.b16 {%0,%1,%2,%3}, [%4];"
                : "=r"(b00), "=r"(b01), "=r"(b10), "=r"(b11)
                : "r"(bAddr0 + kOff));
            uint32_t b20, b21, b30, b31;
            asm volatile(
                "ldmatrix.sync.aligned.m8n8.x4.shared.b16 {%0,%1,%2,%3}, [%4];"
                : "=r"(b20), "=r"(b21), "=r"(b30), "=r"(b31)
                : "r"(bAddr1 + kOff));
            asm volatile(
                "mma.sync.aligned.m16n8k16.row.col.f32.bf16.bf16.f32 "
                "{%0,%1,%2,%3}, {%4,%5,%6,%7}, {%8,%9}, {%0,%1,%2,%3};"
                : "+f"(acc[0][0]), "+f"(acc[0][1]), "+f"(acc[0][2]), "+f"(acc[0][3])
                : "r"(a0), "r"(a1), "r"(a2), "r"(a3), "r"(b00), "r"(b01));
            asm volatile(
                "mma.sync.aligned.m16n8k16.row.col.f32.bf16.bf16.f32 "
                "{%0,%1,%2,%3}, {%4,%5,%6,%7}, {%8,%9}, {%0,%1,%2,%3};"
                : "+f"(acc[1][0]), "+f"(acc[1][1]), "+f"(acc[1][2]), "+f"(acc[1][3])
                : "r"(a0), "r"(a1), "r"(a2), "r"(a3), "r"(b10), "r"(b11));
            asm volatile(
                "mma.sync.aligned.m16n8k16.row.col.f32.bf16.bf16.f32 "
                "{%0,%1,%2,%3}, {%4,%5,%6,%7}, {%8,%9}, {%0,%1,%2,%3};"
                : "+f"(acc[2][0]), "+f"(acc[2][1]), "+f"(acc[2][2]), "+f"(acc[2][3])
                : "r"(a0), "r"(a1), "r"(a2), "r"(a3), "r"(b20), "r"(b21));
            asm volatile(
                "mma.sync.aligned.m16n8k16.row.col.f32.bf16.bf16.f32 "
                "{%0,%1,%2,%3}, {%4,%5,%6,%7}, {%8,%9}, {%0,%1,%2,%3};"
                : "+f"(acc[3][0]), "+f"(acc[3][1]), "+f"(acc[3][2]), "+f"(acc[3][3])
                : "r"(a0), "r"(a1), "r"(a2), "r"(a3), "r"(b30), "r"(b31));
        }
        __syncthreads();   // all reads done before next store overwrites
    }

    float* S = g_S + (size_t)mi * NN * DD;
    int row = i0 + wr * 16 + lr;
    #pragma unroll
    for (int nt = 0; nt < 4; ++nt) {
        int c0 = wc * 32 + nt * 8 + lc * 2;
        *(float2*)&S[(size_t)row * DD + c0] =
            make_float2(acc[nt][0], acc[nt][1]);
        *(float2*)&S[(size_t)(row + 8) * DD + c0] =
            make_float2(acc[nt][2], acc[nt][3]);
    }
}

// ============ kernel Cb: combine S_m into agg ================================
__device__ const float QC[13][6] = {
    {EC0S,        EC1S,        EC2S,        EC3S,         EC4S,         EC5S},
    {2*EC0S,      4*EC1S,      6*EC2S,      8*EC3S,       10*EC4S,      12*EC5S},
    {EC0S,        6*EC1S,      15*EC2S,     28*EC3S,      45*EC4S,      66*EC5S},
    {0.f,         4*EC1S,      20*EC2S,     56*EC3S,      120*EC4S,     220*EC5S},
    {0.f,         EC1S,        15*EC2S,     70*EC3S,      210*EC4S,     495*EC5S},
    {0.f,         0.f,         6*EC2S,      56*EC3S,      252*EC4S,     792*EC5S},
    {0.f,         0.f,         EC2S,        28*EC3S,      210*EC4S,     924*EC5S},
    {0.f,         0.f,         0.f,         8*EC3S,       120*EC4S,     792*EC5S},
    {0.f,         0.f,         0.f,         EC3S,         45*EC4S,      495*EC5S},
    {0.f,         0.f,         0.f,         0.f,          10*EC4S,      220*EC5S},
    {0.f,         0.f,         0.f,         0.f,          EC4S,         66*EC5S},
    {0.f,         0.f,         0.f,         0.f,          0.f,          12*EC5S},
    {0.f,         0.f,         0.f,         0.f,          0.f,          EC5S}
};

__global__ void k_comb() {
    int i = blockIdx.x, d = threadIdx.x;
    float av = g_a[i * DD + d];
    float s0 = g_S0[i];
    float avp[13];
    avp[0] = 1.0f;
    #pragma unroll
    for (int k = 1; k <= 12; ++k) avp[k] = avp[k - 1] * av;

    float acc = 0.0f;
    #pragma unroll
    for (int m = 0; m <= 12; ++m) {
        float w = 0.0f;
        #pragma unroll
        for (int t = 0; t < 6; ++t) {
            if (2 * t + 2 >= m) w = fmaf(QC[m][t], avp[2 * t + 2 - m], w);
        }
        if (m == 0) w = fmaf(CSQ2, av, w);       // C*z term, a-part
        if (m == 1) w += CSQ2;                   // C*z term, c-part
        float Sm = (m == 0) ? s0 : g_S[((size_t)(m - 1) * NN + i) * DD + d];
        acc = fmaf(w, Sm, acc);
    }
    g_agg[i * DD + d] = acc;
}

// ====== kernel C: update+LN (+ a/c of next layer) fused, k-split ============
__global__ void k_upac(const float* __restrict__ Wu,
                       const float* __restrict__ bu,
                       const float* __restrict__ gamma,
                       const float* __restrict__ beta,
                       const float* __restrict__ Wm,
                       const float* __restrict__ bm,
                       int l, int do_next) {
    int i0 = blockIdx.x * ACR;
    int d  = threadIdx.x;
    int ty = threadIdx.y;
    int tid = ty * DD + d;

    __shared__ float hsh[ACR][DD], ash[ACR][DD], newh[ACR][DD];
    __shared__ float red[ACR][ACR][DD];
    __shared__ float rs_m[ACR][4], rs_v[ACR][4];

    {
        int r = tid >> 7, c = tid & 127;
        hsh[r][c] = g_h  [(i0 + r) * DD + c];
        ash[r][c] = g_agg[(i0 + r) * DD + c];
    }
    __syncthreads();

    const float* W1 = Wu + (size_t)l * 2 * DD * DD;
    const float* W2 = W1 + DD * DD;
    {
        float acc[ACR] = {0.f, 0.f, 0.f, 0.f};
        int k0 = ty * 32;
        #pragma unroll 8
        for (int kk = 0; kk < 32; ++kk) {
            int k = k0 + kk;
            float w1 = W1[k * DD + d];
            float w2 = W2[k * DD + d];
            #pragma unroll
            for (int r = 0; r < ACR; ++r) {
                acc[r] = fmaf(hsh[r][k], w1, acc[r]);
                acc[r] = fmaf(ash[r][k], w2, acc[r]);
            }
        }
        #pragma unroll
        for (int r = 0; r < ACR; ++r) red[ty][r][d] = acc[r];
    }
    __syncthreads();

    int r = ty;
    float x = bu[l * DD + d]
            + red[0][r][d] + red[1][r][d] + red[2][r][d] + red[3][r][d];
    x = gelu_exact(x) + hsh[r][d];

    float v = x;
    #pragma unroll
    for (int o = 16; o > 0; o >>= 1) v += __shfl_xor_sync(0xffffffffu, v, o);
    if ((d & 31) == 0) rs_m[r][d >> 5] = v;
    __syncthreads();
    float mean = (rs_m[r][0] + rs_m[r][1] + rs_m[r][2] + rs_m[r][3]) * (1.0f / DD);
    float xm = x - mean;
    float v2 = xm * xm;
    #pragma unroll
    for (int o = 16; o > 0; o >>= 1) v2 += __shfl_xor_sync(0xffffffffu, v2, o);
    if ((d & 31) == 0) rs_v[r][d >> 5] = v2;
    __syncthreads();
    float var = (rs_v[r][0] + rs_v[r][1] + rs_v[r][2] + rs_v[r][3]) * (1.0f / DD);
    float y = xm * rsqrtf(var + 1e-5f) * gamma[l * DD + d] + beta[l * DD + d];
    g_h[(i0 + r) * DD + d] = y;
    newh[r][d] = y;
    __syncthreads();

    if (do_next) {
        const float* WA = Wm + (size_t)(l + 1) * 2 * DD * DD;
        const float* WC = WA + DD * DD;
        float aa[ACR] = {0.f, 0.f, 0.f, 0.f};
        float cc[ACR] = {0.f, 0.f, 0.f, 0.f};
        int k0 = ty * 32;
        #pragma unroll 8
        for (int kk = 0; kk < 32; ++kk) {
            int k = k0 + kk;
            float wa = WA[k * DD + d];
            float wc = WC[k * DD + d];
            #pragma unroll
            for (int rr = 0; rr < ACR; ++rr) {
                float hv = newh[rr][k];
                aa[rr] = fmaf(hv, wa, aa[rr]);
                cc[rr] = fmaf(hv, wc, cc[rr]);
            }
        }
        #pragma unroll
        for (int rr = 0; rr < ACR; ++rr) red[ty][rr][d] = aa[rr];
        __syncthreads();
        g_a[(i0 + ty) * DD + d] =
            (red[0][ty][d] + red[1][ty][d] + red[2][ty][d] + red[3][ty][d]) * CSQ2;
        __syncthreads();
        #pragma unroll
        for (int rr = 0; rr < ACR; ++rr) red[ty][rr][d] = cc[rr];
        __syncthreads();
        g_cb[(i0 + ty) * DD + d] =
            (red[0][ty][d] + red[1][ty][d] + red[2][ty][d] + red[3][ty][d]
             + bm[(l + 1) * DD + d]) * CSQ2;
    }
}

// ---------------- kernel D: output heads ------------------------------------
__global__ void k_heads(const float* __restrict__ Wt,
                        const float* __restrict__ bt,
                        const float* __restrict__ Wi,
                        const float* __restrict__ bi,
                        const float* __restrict__ Wa,
                        const float* __restrict__ ba,
                        float* __restrict__ out) {
    int i = blockIdx.x;
    int d = threadIdx.x;
    __shared__ float hsh[DD];
    float hv = g_h[i * DD + d];
    hsh[d] = hv;
    __syncthreads();

    out[NN + NN * 5 + NN * 5 + i * DD + d] = hv;

    if (d < 5) {
        float s = bi[d];
        #pragma unroll 8
        for (int k = 0; k < DD; ++k) s = fmaf(hsh[k], Wi[k * 5 + d], s);
        out[NN + i * 5 + d] = s;
        float s2 = ba[d];
        #pragma unroll 8
        for (int k = 0; k < DD; ++k) s2 = fmaf(hsh[k], Wa[k * 5 + d], s2);
        out[NN + NN * 5 + i * 5 + d] = s2;
    }
    if (d == 5) {
        float s = bt[0];
        #pragma unroll 8
        for (int k = 0; k < DD; ++k) s = fmaf(hsh[k], Wt[k], s);
        out[i] = 5.0f / (1.0f + expf(-s));
    }
}

// ---------------- launcher ---------------------------------------------------
extern "C" void kernel_launch(void* const* d_in, const int* in_sizes, int n_in,
                              void* d_out, int out_size) {
    const float* nf    = (const float*)d_in[0];
    const float* adj   = (const float*)d_in[1];
    const float* Wp    = (const float*)d_in[2];
    const float* bp    = (const float*)d_in[3];
    const float* Wm    = (const float*)d_in[4];
    const float* bm    = (const float*)d_in[5];
    const float* Wu    = (const float*)d_in[6];
    const float* bu    = (const float*)d_in[7];
    const float* gamma = (const float*)d_in[8];
    const float* beta  = (const float*)d_in[9];
    const float* Wt    = (const float*)d_in[10];
    const float* bt    = (const float*)d_in[11];
    const float* Wi    = (const float*)d_in[12];
    const float* bi    = (const float*)d_in[13];
    const float* Wa    = (const float*)d_in[14];
    const float* ba    = (const float*)d_in[15];
    float* out = (float*)d_out;

    k_prep<<<NN, 256>>>(adj);
    dim3 gblk(DD, ACR);
    k_proj_ac<<<NN / ACR, gblk>>>(nf, Wp, bp, Wm, bm);
    for (int l = 0; l < NL; ++l) {
        k_pow<<<dim3(NN / 32, DD / 32), dim3(32, 32)>>>();
        k_gemm<<<dim3(32, MPOW), 256>>>();
        k_comb<<<NN, DD>>>();
        k_upac<<<NN / ACR, gblk>>>(Wu, bu, gamma, beta, Wm, bm, l, (l + 1 < NL) ? 1 : 0);
    }
    k_heads<<<NN, DD>>>(Wt, bt, Wi, bi, Wa, ba, out);
}